// round 9
// baseline (speedup 1.0000x reference)
#include <cuda_runtime.h>
#include <stdint.h>

#define NTHREADS 512
#define NN 32768
#define NBINS 4096
#define PRE_NMS_K 300
#define POST_KK 100
#define CAND_CAP 4096       /* smem selected-candidate cap */
#define MW 5                /* ceil(300/64) */
#define B_MAX 64
#define SCAN_PARTS 4
#define PCAP 2048           /* per-(batch,part) candidate cap */
#define GTOT (SCAN_PARTS * PCAP)   /* 8192 per batch */

/* ---- global scratch (allowed: __device__ arrays) ---- */
__device__ unsigned long long g_cand[B_MAX * GTOT];
__device__ int g_pcnt09[B_MAX * SCAN_PARTS];   /* true counts (may exceed PCAP) */
__device__ int g_pcnt005[B_MAX * SCAN_PARTS];

/* ---- finalize smem layout (bytes) ---- */
#define CANDR_OFF  0                               /* gathered raw candidates */
#define HIST_OFF   (CANDR_OFF + GTOT * 8)          /* 65536 */
#define CANDS_OFF  (HIST_OFF + NBINS * 4)          /* 81920 */
#define BX1_OFF    (CANDS_OFF + CAND_CAP * 8)      /* 114688 */
#define BY1_OFF    (BX1_OFF + PRE_NMS_K * 4)
#define BX2_OFF    (BY1_OFF + PRE_NMS_K * 4)
#define BY2_OFF    (BX2_OFF + PRE_NMS_K * 4)
#define BAREA_OFF  (BY2_OFF + PRE_NMS_K * 4)
#define MASK_OFF   (BAREA_OFF + PRE_NMS_K * 4)
#define MASK_OFF8  ((MASK_OFF + 7) & ~7)
#define KEEP_OFF   (MASK_OFF8 + PRE_NMS_K * MW * 8)
#define WS_OFF     (KEEP_OFF + MW * 8)
#define SCAL_OFF   (WS_OFF + 16 * 4)
#define SMEM_BYTES (SCAL_OFF + 8 * 4)

/* ---- scan smem ---- */
struct ScanSmem {
    unsigned long long list[PCAP];
    int cnt;
    int c005;
};

__global__ void __launch_bounds__(NTHREADS)
scan_kernel(const float* __restrict__ cls_prob) {
    __shared__ ScanSmem ss;
    const int part = blockIdx.x;
    const int b    = blockIdx.y;
    const int tid  = threadIdx.x;
    const int lane = tid & 31;
    const int ITEMS = NN / SCAN_PARTS;          /* 8192 */
    const int jbase = part * ITEMS;
    const float4* cp4 = (const float4*)(cls_prob + (size_t)b * (NN * 2))
                        + (size_t)part * (ITEMS / 2);
    if (tid == 0) { ss.cnt = 0; ss.c005 = 0; }
    __syncthreads();

    int c005 = 0;
#pragma unroll
    for (int k = 0; k < (ITEMS / 2) / NTHREADS; k++) {   /* 8 iters */
        int m = tid + k * NTHREADS;
        float4 v = cp4[m];
        c005 += (v.y >= 0.05f) + (v.w >= 0.05f);
#pragma unroll
        for (int h = 0; h < 2; h++) {
            float s = h ? v.w : v.y;
            if (s >= 0.9f) {
                int j = jbase + 2 * m + h;
                int p = atomicAdd(&ss.cnt, 1);
                if (p < PCAP)
                    ss.list[p] = ((unsigned long long)__float_as_uint(s) << 32) |
                                 (unsigned long long)(0xFFFFFFFFu - (uint32_t)j);
            }
        }
    }
#pragma unroll
    for (int off = 16; off >= 1; off >>= 1)
        c005 += __shfl_down_sync(0xFFFFFFFFu, c005, off);
    if (lane == 0 && c005) atomicAdd(&ss.c005, c005);
    __syncthreads();

    int n = ss.cnt < PCAP ? ss.cnt : PCAP;
    unsigned long long* dst = g_cand + ((size_t)b * SCAN_PARTS + part) * PCAP;
    for (int i = tid; i < n; i += NTHREADS) dst[i] = ss.list[i];
    if (tid == 0) {
        g_pcnt09[b * SCAN_PARTS + part]  = ss.cnt;   /* true count */
        g_pcnt005[b * SCAN_PARTS + part] = ss.c005;
    }
}

__global__ void __launch_bounds__(NTHREADS, 1)
finalize_kernel(const float* __restrict__ cls_prob,
                const float* __restrict__ boxes,
                const float* __restrict__ deltas,
                const float* __restrict__ im_info,
                float* __restrict__ out)
{
    extern __shared__ unsigned char smem[];
    unsigned long long* candR = (unsigned long long*)(smem + CANDR_OFF);
    int*                hist  = (int*)(smem + HIST_OFF);
    unsigned long long* cand  = (unsigned long long*)(smem + CANDS_OFF);
    float*              bx1   = (float*)(smem + BX1_OFF);
    float*              by1   = (float*)(smem + BY1_OFF);
    float*              bx2   = (float*)(smem + BX2_OFF);
    float*              by2   = (float*)(smem + BY2_OFF);
    float*              barea = (float*)(smem + BAREA_OFF);
    unsigned long long* maskA = (unsigned long long*)(smem + MASK_OFF8);
    unsigned long long* keepw = (unsigned long long*)(smem + KEEP_OFF);
    int*                wsums = (int*)(smem + WS_OFF);
    int*                scal  = (int*)(smem + SCAL_OFF); /* 0=selCnt 1=bstar */

    const int b    = blockIdx.x;
    const int tid  = threadIdx.x;
    const int lane = tid & 31;
    const int wrp  = tid >> 5;

    /* part counts -> totals, bases, overflow check */
    int pcnt[SCAN_PARTS], pbase[SCAN_PARTS];
    int cnt09 = 0, cnt005 = 0, n09 = 0;
    bool overflow = false;
#pragma unroll
    for (int p = 0; p < SCAN_PARTS; p++) {
        int c = g_pcnt09[b * SCAN_PARTS + p];
        cnt09 += c;
        cnt005 += g_pcnt005[b * SCAN_PARTS + p];
        if (c > PCAP) { overflow = true; c = PCAP; }
        pbase[p] = n09; pcnt[p] = c; n09 += c;
    }
    const int target0 = cnt005 < PRE_NMS_K ? cnt005 : PRE_NMS_K;
    const bool fast = (cnt09 >= target0) && !overflow;

    for (int i = tid; i < NBINS; i += NTHREADS) hist[i] = 0;
    if (tid == 0) { scal[0] = 0; scal[1] = NBINS; }

    /* ---- gather candidates to smem (fast path) ---- */
    if (fast) {
        for (int i = tid; i < GTOT; i += NTHREADS) {
            int p = i / PCAP, idx = i % PCAP;
            if (idx < pcnt[p])
                candR[pbase[p] + idx] =
                    g_cand[((size_t)b * SCAN_PARTS + p) * PCAP + idx];
        }
    }
    __syncthreads();

    /* ---- build histogram ---- */
    if (fast) {
        for (int i = tid; i < n09; i += NTHREADS) {
            float s = __uint_as_float((uint32_t)(candR[i] >> 32));
            int bin = (int)__fmul_rn(__fsub_rn(s, 0.9f), 40960.0f);
            bin = bin < NBINS - 1 ? bin : NBINS - 1;
            atomicAdd(&hist[bin], 1);
        }
    } else {
        const float2* cp = (const float2*)(cls_prob + (size_t)b * (NN * 2));
        for (int k = 0; k < NN / NTHREADS; k++) {
            int j = tid + k * NTHREADS;
            float s = cp[j].y;
            if (s >= 0.05f) {
                int bin = (int)__fmul_rn(__fsub_rn(s, 0.05f), (4096.0f / 0.95f));
                bin = bin < NBINS - 1 ? bin : NBINS - 1;
                atomicAdd(&hist[bin], 1);
            }
        }
    }
    __syncthreads();

    /* ---- chunk sums (top-down) + shfl block scan -> bstar ---- */
    int base8 = NBINS - 8 * (tid + 1);
    int4 h0 = *(int4*)&hist[base8];
    int4 h1 = *(int4*)&hist[base8 + 4];
    int s8 = h0.x + h0.y + h0.z + h0.w + h1.x + h1.y + h1.z + h1.w;
    int v = s8;
#pragma unroll
    for (int off = 1; off < 32; off <<= 1) {
        int n = __shfl_up_sync(0xFFFFFFFFu, v, off);
        if (lane >= off) v += n;
    }
    if (lane == 31) wsums[wrp] = v;
    __syncthreads();
    if (wrp == 0) {
        int t = (lane < 16) ? wsums[lane] : 0;
#pragma unroll
        for (int off = 1; off < 16; off <<= 1) {
            int n = __shfl_up_sync(0xFFFFFFFFu, t, off);
            if (lane >= off) t += n;
        }
        if (lane < 16) wsums[lane] = t;
    }
    __syncthreads();
    int inc = v + (wrp > 0 ? wsums[wrp - 1] : 0);
    int total = wsums[15];
    int target = total < PRE_NMS_K ? total : PRE_NMS_K;
    {
        int exc = inc - s8;
        if (target > 0 && exc < target && target <= inc) {
            int cum = exc, bsel = base8;
            for (int u = 7; u >= 0; u--) {
                cum += hist[base8 + u];
                if (cum >= target) { bsel = base8 + u; break; }
            }
            scal[1] = bsel;
        }
    }
    __syncthreads();
    int bstar = scal[1];

    /* ---- collect selected candidates ---- */
    if (fast) {
        for (int i = tid; i < n09; i += NTHREADS) {
            unsigned long long kk = candR[i];
            float s = __uint_as_float((uint32_t)(kk >> 32));
            int bin = (int)__fmul_rn(__fsub_rn(s, 0.9f), 40960.0f);
            bin = bin < NBINS - 1 ? bin : NBINS - 1;
            if (bin >= bstar) {
                int p = atomicAdd(&scal[0], 1);
                if (p < CAND_CAP) cand[p] = kk;
            }
        }
    } else {
        const float2* cp = (const float2*)(cls_prob + (size_t)b * (NN * 2));
        for (int k = 0; k < NN / NTHREADS; k++) {
            int j = tid + k * NTHREADS;
            float s = cp[j].y;
            if (s >= 0.05f) {
                int bin = (int)__fmul_rn(__fsub_rn(s, 0.05f), (4096.0f / 0.95f));
                bin = bin < NBINS - 1 ? bin : NBINS - 1;
                if (bin >= bstar) {
                    int p = atomicAdd(&scal[0], 1);
                    if (p < CAND_CAP)
                        cand[p] = ((unsigned long long)__float_as_uint(s) << 32) |
                                  (unsigned long long)(0xFFFFFFFFu - (uint32_t)j);
                }
            }
        }
    }
    __syncthreads();
    int cnt = scal[0] < CAND_CAP ? scal[0] : CAND_CAP;
    int M = 512;
    while (M < cnt) M <<= 1;
    for (int i = cnt + tid; i < M; i += NTHREADS) cand[i] = 0ull;
    __syncthreads();

    /* ---- Bitonic sort descending: (score desc, idx asc) == jax top_k order ---- */
    if (M == 512) {
        unsigned long long a = cand[tid];
#pragma unroll
        for (int k2 = 2; k2 <= 32; k2 <<= 1) {
#pragma unroll
            for (int jj = 16; jj >= 1; jj >>= 1) {
                if (jj <= (k2 >> 1)) {
                    unsigned long long c = __shfl_xor_sync(0xFFFFFFFFu, a, jj);
                    bool keepmax = (((tid & k2) == 0) == ((tid & jj) == 0));
                    unsigned long long mx = a > c ? a : c;
                    unsigned long long mn = a > c ? c : a;
                    a = keepmax ? mx : mn;
                }
            }
        }
        cand[tid] = a;
        __syncthreads();
        for (int k2 = 64; k2 <= 512; k2 <<= 1) {
            for (int jj = k2 >> 1; jj >= 32; jj >>= 1) {
                int l = tid ^ jj;
                if (l > tid) {
                    unsigned long long x = cand[tid];
                    unsigned long long y = cand[l];
                    bool up = ((tid & k2) == 0);
                    if (up ? (x < y) : (x > y)) { cand[tid] = y; cand[l] = x; }
                }
                __syncthreads();
            }
            a = cand[tid];
#pragma unroll
            for (int jj = 16; jj >= 1; jj >>= 1) {
                unsigned long long c = __shfl_xor_sync(0xFFFFFFFFu, a, jj);
                bool keepmax = (((tid & k2) == 0) == ((tid & jj) == 0));
                unsigned long long mx = a > c ? a : c;
                unsigned long long mn = a > c ? c : a;
                a = keepmax ? mx : mn;
            }
            cand[tid] = a;
            __syncthreads();
        }
    } else {
        for (int k2 = 2; k2 <= M; k2 <<= 1) {
            for (int jj = k2 >> 1; jj > 0; jj >>= 1) {
                for (int i = tid; i < M; i += NTHREADS) {
                    int l = i ^ jj;
                    if (l > i) {
                        unsigned long long a2 = cand[i];
                        unsigned long long c2 = cand[l];
                        bool up = ((i & k2) == 0);
                        if (up ? (a2 < c2) : (a2 > c2)) { cand[i] = c2; cand[l] = a2; }
                    }
                }
                __syncthreads();
            }
        }
    }

    int L = cnt < PRE_NMS_K ? cnt : PRE_NMS_K;

    /* ---- Decode + clip selected boxes (rn intrinsics: no FMA contraction) ---- */
    if (tid < L) {
        unsigned long long kk = cand[tid];
        int j = (int)(0xFFFFFFFFu - (uint32_t)(kk & 0xFFFFFFFFull));
        float4 bb = *(const float4*)(boxes  + ((size_t)b * NN + j) * 4);
        float4 dd = *(const float4*)(deltas + ((size_t)b * NN + j) * 4);
        float w  = __fadd_rn(__fsub_rn(bb.z, bb.x), 1.0f);
        float h  = __fadd_rn(__fsub_rn(bb.w, bb.y), 1.0f);
        float cx = __fadd_rn(bb.x, __fmul_rn(0.5f, w));
        float cy = __fadd_rn(bb.y, __fmul_rn(0.5f, h));
        float d0 = __fmul_rn(dd.x, 0.1f);
        float d1 = __fmul_rn(dd.y, 0.1f);
        float d2 = __fmul_rn(dd.z, 0.2f);
        float d3 = __fmul_rn(dd.w, 0.2f);
        float pcx = __fadd_rn(__fmul_rn(d0, w), cx);
        float pcy = __fadd_rn(__fmul_rn(d1, h), cy);
        float pw  = __fmul_rn((float)exp((double)d2), w);
        float ph  = __fmul_rn((float)exp((double)d3), h);
        float x1 = __fsub_rn(pcx, __fmul_rn(0.5f, pw));
        float y1 = __fsub_rn(pcy, __fmul_rn(0.5f, ph));
        float x2 = __fadd_rn(pcx, __fmul_rn(0.5f, pw));
        float y2 = __fadd_rn(pcy, __fmul_rn(0.5f, ph));
        float hmax = __fsub_rn(im_info[b * 3 + 0], 1.0f);
        float wmax = __fsub_rn(im_info[b * 3 + 1], 1.0f);
        x1 = fminf(fmaxf(x1, 0.0f), wmax);
        y1 = fminf(fmaxf(y1, 0.0f), hmax);
        x2 = fminf(fmaxf(x2, 0.0f), wmax);
        y2 = fminf(fmaxf(y2, 0.0f), hmax);
        bx1[tid] = x1; by1[tid] = y1; bx2[tid] = x2; by2[tid] = y2;
        barea[tid] = __fmul_rn(__fadd_rn(__fsub_rn(x2, x1), 1.0f),
                               __fadd_rn(__fsub_rn(y2, y1), 1.0f));
    }
    __syncthreads();

    /* ---- IoU suppression bitmasks: mask[i] bit j set iff j>i && iou>0.3 ---- */
    for (int item = tid; item < PRE_NMS_K * MW; item += NTHREADS) {
        int i = item / MW, w = item % MW;
        unsigned long long bits = 0ull;
        if (i < L) {
            float xi1 = bx1[i], yi1 = by1[i], xi2 = bx2[i], yi2 = by2[i], ai = barea[i];
            int j0 = w * 64;
            int jend = (j0 + 64 < L) ? j0 + 64 : L;
            for (int j = (j0 > i + 1 ? j0 : i + 1); j < jend; j++) {
                float xx1 = fmaxf(xi1, bx1[j]);
                float yy1 = fmaxf(yi1, by1[j]);
                float xx2 = fminf(xi2, bx2[j]);
                float yy2 = fminf(yi2, by2[j]);
                float iw = fmaxf(__fadd_rn(__fsub_rn(xx2, xx1), 1.0f), 0.0f);
                float ih = fmaxf(__fadd_rn(__fsub_rn(yy2, yy1), 1.0f), 0.0f);
                float inter = __fmul_rn(iw, ih);
                float uni = __fsub_rn(__fadd_rn(ai, barea[j]), inter);
                float iou = __fdiv_rn(inter, uni);
                if (iou > 0.3f) bits |= 1ull << (j - j0);
            }
        }
        maskA[item] = bits;
    }
    __syncthreads();

    /* ---- Serial greedy NMS, chunked to keep LDS off the decision chain ---- */
    if (tid == 0) {
        unsigned long long r[MW] = {0ull, 0ull, 0ull, 0ull, 0ull};
#pragma unroll
        for (int w = 0; w < MW; w++) {
            int i0w = w * 64;
            if (i0w < L) {
                int iend = (i0w + 64 < L) ? i0w + 64 : L;
                for (int c0 = i0w; c0 < iend; c0 += 16) {
                    int ce = (c0 + 16 < iend) ? c0 + 16 : iend;
                    unsigned long long mm[16];
#pragma unroll
                    for (int t = 0; t < 16; t++)
                        mm[t] = (c0 + t < ce) ? maskA[(c0 + t) * MW + w] : 0ull;
#pragma unroll
                    for (int t = 0; t < 16; t++) {
                        int i = c0 + t;
                        if (i < ce && !((r[w] >> (i - i0w)) & 1ull))
                            r[w] |= mm[t];
                    }
                }
                int nb = iend - i0w;
                unsigned long long vm = (nb >= 64) ? ~0ull : ((1ull << nb) - 1ull);
                unsigned long long kw = (~r[w]) & vm;
                while (kw) {
                    int t = __ffsll((long long)kw) - 1;
                    kw &= kw - 1ull;
                    const unsigned long long* m = maskA + (i0w + t) * MW;
#pragma unroll
                    for (int w2 = 0; w2 < MW; w2++)
                        if (w2 > w) r[w2] |= m[w2];
                }
            }
        }
#pragma unroll
        for (int w = 0; w < MW; w++) {
            int lo = w * 64;
            unsigned long long vm = (L <= lo) ? 0ull
                                  : ((L - lo >= 64) ? ~0ull : ((1ull << (L - lo)) - 1ull));
            keepw[w] = (~r[w]) & vm;
        }
    }
    __syncthreads();

    /* ---- Output: zero then scatter kept rows by rank ---- */
    float* outb = out + (size_t)b * (POST_KK * 5);
    for (int t = tid; t < POST_KK * 5; t += NTHREADS) outb[t] = 0.0f;
    __syncthreads();
    if (tid < L) {
        int w = tid >> 6, bp = tid & 63;
        if ((keepw[w] >> bp) & 1ull) {
            int rank = 0;
            for (int u = 0; u < w; u++) rank += __popcll(keepw[u]);
            rank += __popcll(keepw[w] & ((1ull << bp) - 1ull));
            if (rank < POST_KK) {
                float* row = outb + rank * 5;
                row[0] = (float)b;
                row[1] = bx1[tid];
                row[2] = by1[tid];
                row[3] = bx2[tid];
                row[4] = by2[tid];
            }
        }
    }
}

extern "C" void kernel_launch(void* const* d_in, const int* in_sizes, int n_in,
                              void* d_out, int out_size) {
    const float* cls_prob = (const float*)d_in[0];
    const float* boxes    = (const float*)d_in[1];
    const float* deltas   = (const float*)d_in[2];
    const float* im_info  = (const float*)d_in[3];
    int B = in_sizes[3] / 3;
    if (B > B_MAX) B = B_MAX;
    cudaFuncSetAttribute(finalize_kernel,
                         cudaFuncAttributeMaxDynamicSharedMemorySize, SMEM_BYTES);
    scan_kernel<<<dim3(SCAN_PARTS, B), NTHREADS>>>(cls_prob);
    finalize_kernel<<<B, NTHREADS, SMEM_BYTES>>>(cls_prob, boxes, deltas,
                                                 im_info, (float*)d_out);
}

// round 12
// speedup vs baseline: 1.4952x; 1.4952x over previous
#include <cuda_runtime.h>
#include <stdint.h>

#define NTHREADS 512
#define NN 32768
#define NBINS 4096
#define PRE_NMS_K 300
#define POST_KK 100
#define CAND_CAP 4096
#define MW 5  /* ceil(300/64) */

/* ---- shared memory layout (bytes) ---- */
#define CAND_OFF   0                                /* raw s>=0.9 candidates */
#define CAND2_OFF  (CAND_OFF + CAND_CAP * 8)        /* 32768: selected */
#define HIST_OFF   (CAND2_OFF + CAND_CAP * 8)       /* 65536 */
#define BX1_OFF    (HIST_OFF + NBINS * 4)           /* 81920 */
#define BY1_OFF    (BX1_OFF + PRE_NMS_K * 4)
#define BX2_OFF    (BY1_OFF + PRE_NMS_K * 4)
#define BY2_OFF    (BX2_OFF + PRE_NMS_K * 4)
#define BAREA_OFF  (BY2_OFF + PRE_NMS_K * 4)
#define MASK_OFF   (BAREA_OFF + PRE_NMS_K * 4)      /* 87920, 8B aligned */
#define KEEP_OFF   (MASK_OFF + PRE_NMS_K * MW * 8)  /* 99920 */
#define WS_OFF     (KEEP_OFF + MW * 8)
#define SCAL_OFF   (WS_OFF + 16 * 4)
#define SMEM_BYTES (SCAL_OFF + 8 * 4)               /* ~100 KB */

__global__ void __launch_bounds__(NTHREADS, 1)
proposal_kernel(const float* __restrict__ cls_prob,
                const float* __restrict__ boxes,
                const float* __restrict__ deltas,
                const float* __restrict__ im_info,
                float* __restrict__ out)
{
    extern __shared__ unsigned char smem[];
    unsigned long long* cand  = (unsigned long long*)(smem + CAND_OFF);
    unsigned long long* cand2 = (unsigned long long*)(smem + CAND2_OFF);
    int*                hist  = (int*)(smem + HIST_OFF);
    float*              bx1   = (float*)(smem + BX1_OFF);
    float*              by1   = (float*)(smem + BY1_OFF);
    float*              bx2   = (float*)(smem + BX2_OFF);
    float*              by2   = (float*)(smem + BY2_OFF);
    float*              barea = (float*)(smem + BAREA_OFF);
    unsigned long long* maskA = (unsigned long long*)(smem + MASK_OFF);
    unsigned long long* keepw = (unsigned long long*)(smem + KEEP_OFF);
    int*                wsums = (int*)(smem + WS_OFF);
    int*                scal  = (int*)(smem + SCAL_OFF);
    /* scal: 0=cnt09(push), 1=bstar, 2=selCnt, 3=c005 */

    const int b    = blockIdx.x;
    const int tid  = threadIdx.x;
    const int lane = tid & 31;
    const int wrp  = tid >> 5;
    const unsigned lmlt = (1u << lane) - 1u;

    for (int i = tid; i < NBINS; i += NTHREADS) hist[i] = 0;
    if (tid == 0) { scal[0] = 0; scal[1] = NBINS; scal[2] = 0; scal[3] = 0; }
    __syncthreads();

    /* ---- Phase A: stream scores, push s>=0.9 candidates (warp-aggregated) ---- */
    const float4* cp4 = (const float4*)(cls_prob + (size_t)b * (NN * 2));
    int c005 = 0;
#pragma unroll 4
    for (int k = 0; k < (NN / 2) / NTHREADS; k++) {      /* 32 iters */
        int m = tid + k * NTHREADS;
        float4 v = cp4[m];
        float s0 = v.y, s1 = v.w;        /* cls_prob[b, 2m, 1], [b, 2m+1, 1] */
        c005 += (s0 >= 0.05f) + (s1 >= 0.05f);
#pragma unroll
        for (int h = 0; h < 2; h++) {
            float s = h ? s1 : s0;
            bool p = (s >= 0.9f);
            unsigned bl = __ballot_sync(0xFFFFFFFFu, p);
            if (bl) {
                int base = 0;
                if (lane == 0) base = atomicAdd(&scal[0], __popc(bl));
                base = __shfl_sync(0xFFFFFFFFu, base, 0);
                if (p) {
                    int off = base + __popc(bl & lmlt);
                    if (off < CAND_CAP) {
                        int j = 2 * m + h;
                        cand[off] = ((unsigned long long)__float_as_uint(s) << 32) |
                                    (unsigned long long)(0xFFFFFFFFu - (uint32_t)j);
                    }
                }
            }
        }
    }
#pragma unroll
    for (int off = 16; off >= 1; off >>= 1)
        c005 += __shfl_down_sync(0xFFFFFFFFu, c005, off);
    if (lane == 0 && c005) atomicAdd(&scal[3], c005);
    __syncthreads();

    const int cnt09  = scal[0];
    const int cnt005 = scal[3];
    const int n09 = cnt09 < CAND_CAP ? cnt09 : CAND_CAP;
    const int target0 = cnt005 < PRE_NMS_K ? cnt005 : PRE_NMS_K;
    const bool fast = (cnt09 >= target0) && (cnt09 <= CAND_CAP);

    /* ---- histogram ---- */
    if (fast) {
        for (int i = tid; i < n09; i += NTHREADS) {
            float s = __uint_as_float((uint32_t)(cand[i] >> 32));
            int bin = (int)__fmul_rn(__fsub_rn(s, 0.9f), 40960.0f);
            bin = bin < NBINS - 1 ? bin : NBINS - 1;
            atomicAdd(&hist[bin], 1);
        }
    } else {
        const float2* cp = (const float2*)(cls_prob + (size_t)b * (NN * 2));
        for (int k = 0; k < NN / NTHREADS; k++) {
            int j = tid + k * NTHREADS;
            float s = cp[j].y;
            if (s >= 0.05f) {
                int bin = (int)__fmul_rn(__fsub_rn(s, 0.05f), (4096.0f / 0.95f));
                bin = bin < NBINS - 1 ? bin : NBINS - 1;
                atomicAdd(&hist[bin], 1);
            }
        }
    }
    __syncthreads();

    /* ---- chunk sums (top-down) + shfl block scan -> bstar ---- */
    int base8 = NBINS - 8 * (tid + 1);
    int4 h0 = *(int4*)&hist[base8];
    int4 h1 = *(int4*)&hist[base8 + 4];
    int s8 = h0.x + h0.y + h0.z + h0.w + h1.x + h1.y + h1.z + h1.w;
    int v = s8;
#pragma unroll
    for (int off = 1; off < 32; off <<= 1) {
        int n = __shfl_up_sync(0xFFFFFFFFu, v, off);
        if (lane >= off) v += n;
    }
    if (lane == 31) wsums[wrp] = v;
    __syncthreads();
    if (wrp == 0) {
        int t = (lane < 16) ? wsums[lane] : 0;
#pragma unroll
        for (int off = 1; off < 16; off <<= 1) {
            int n = __shfl_up_sync(0xFFFFFFFFu, t, off);
            if (lane >= off) t += n;
        }
        if (lane < 16) wsums[lane] = t;
    }
    __syncthreads();
    int inc = v + (wrp > 0 ? wsums[wrp - 1] : 0);
    int total = wsums[15];
    int target = total < PRE_NMS_K ? total : PRE_NMS_K;
    {
        int exc = inc - s8;
        if (target > 0 && exc < target && target <= inc) {
            int cum = exc, bsel = base8;
            for (int u = 7; u >= 0; u--) {
                cum += hist[base8 + u];
                if (cum >= target) { bsel = base8 + u; break; }
            }
            scal[1] = bsel;
        }
    }
    __syncthreads();
    int bstar = scal[1];

    /* ---- compact selected candidates into cand2 ---- */
    if (fast) {
        for (int i = tid; i < n09; i += NTHREADS) {
            unsigned long long kk = cand[i];
            float s = __uint_as_float((uint32_t)(kk >> 32));
            int bin = (int)__fmul_rn(__fsub_rn(s, 0.9f), 40960.0f);
            bin = bin < NBINS - 1 ? bin : NBINS - 1;
            if (bin >= bstar) {
                int p = atomicAdd(&scal[2], 1);
                if (p < CAND_CAP) cand2[p] = kk;
            }
        }
    } else {
        const float2* cp = (const float2*)(cls_prob + (size_t)b * (NN * 2));
        for (int k = 0; k < NN / NTHREADS; k++) {
            int j = tid + k * NTHREADS;
            float s = cp[j].y;
            if (s >= 0.05f) {
                int bin = (int)__fmul_rn(__fsub_rn(s, 0.05f), (4096.0f / 0.95f));
                bin = bin < NBINS - 1 ? bin : NBINS - 1;
                if (bin >= bstar) {
                    int p = atomicAdd(&scal[2], 1);
                    if (p < CAND_CAP)
                        cand2[p] = ((unsigned long long)__float_as_uint(s) << 32) |
                                   (unsigned long long)(0xFFFFFFFFu - (uint32_t)j);
                }
            }
        }
    }
    __syncthreads();
    int cnt = scal[2] < CAND_CAP ? scal[2] : CAND_CAP;
    int M = 512;
    while (M < cnt) M <<= 1;
    for (int i = cnt + tid; i < M; i += NTHREADS) cand2[i] = 0ull;
    __syncthreads();

    /* ---- Bitonic sort descending: (score desc, idx asc) == jax top_k order ---- */
    if (M == 512) {
        unsigned long long a = cand2[tid];
#pragma unroll
        for (int k2 = 2; k2 <= 32; k2 <<= 1) {
#pragma unroll
            for (int jj = 16; jj >= 1; jj >>= 1) {
                if (jj <= (k2 >> 1)) {
                    unsigned long long c = __shfl_xor_sync(0xFFFFFFFFu, a, jj);
                    bool keepmax = (((tid & k2) == 0) == ((tid & jj) == 0));
                    unsigned long long mx = a > c ? a : c;
                    unsigned long long mn = a > c ? c : a;
                    a = keepmax ? mx : mn;
                }
            }
        }
        cand2[tid] = a;
        __syncthreads();
        for (int k2 = 64; k2 <= 512; k2 <<= 1) {
            for (int jj = k2 >> 1; jj >= 32; jj >>= 1) {
                int l = tid ^ jj;
                if (l > tid) {
                    unsigned long long x = cand2[tid];
                    unsigned long long y = cand2[l];
                    bool up = ((tid & k2) == 0);
                    if (up ? (x < y) : (x > y)) { cand2[tid] = y; cand2[l] = x; }
                }
                __syncthreads();
            }
            a = cand2[tid];
#pragma unroll
            for (int jj = 16; jj >= 1; jj >>= 1) {
                unsigned long long c = __shfl_xor_sync(0xFFFFFFFFu, a, jj);
                bool keepmax = (((tid & k2) == 0) == ((tid & jj) == 0));
                unsigned long long mx = a > c ? a : c;
                unsigned long long mn = a > c ? c : a;
                a = keepmax ? mx : mn;
            }
            cand2[tid] = a;
            __syncthreads();
        }
    } else {
        for (int k2 = 2; k2 <= M; k2 <<= 1) {
            for (int jj = k2 >> 1; jj > 0; jj >>= 1) {
                for (int i = tid; i < M; i += NTHREADS) {
                    int l = i ^ jj;
                    if (l > i) {
                        unsigned long long a2 = cand2[i];
                        unsigned long long c2 = cand2[l];
                        bool up = ((i & k2) == 0);
                        if (up ? (a2 < c2) : (a2 > c2)) { cand2[i] = c2; cand2[l] = a2; }
                    }
                }
                __syncthreads();
            }
        }
    }

    int L = cnt < PRE_NMS_K ? cnt : PRE_NMS_K;

    /* ---- Decode + clip selected boxes (rn intrinsics: no FMA contraction) ---- */
    if (tid < L) {
        unsigned long long kk = cand2[tid];
        int j = (int)(0xFFFFFFFFu - (uint32_t)(kk & 0xFFFFFFFFull));
        float4 bb = *(const float4*)(boxes  + ((size_t)b * NN + j) * 4);
        float4 dd = *(const float4*)(deltas + ((size_t)b * NN + j) * 4);
        float w  = __fadd_rn(__fsub_rn(bb.z, bb.x), 1.0f);
        float h  = __fadd_rn(__fsub_rn(bb.w, bb.y), 1.0f);
        float cx = __fadd_rn(bb.x, __fmul_rn(0.5f, w));
        float cy = __fadd_rn(bb.y, __fmul_rn(0.5f, h));
        float d0 = __fmul_rn(dd.x, 0.1f);
        float d1 = __fmul_rn(dd.y, 0.1f);
        float d2 = __fmul_rn(dd.z, 0.2f);
        float d3 = __fmul_rn(dd.w, 0.2f);
        float pcx = __fadd_rn(__fmul_rn(d0, w), cx);
        float pcy = __fadd_rn(__fmul_rn(d1, h), cy);
        float pw  = __fmul_rn((float)exp((double)d2), w);
        float ph  = __fmul_rn((float)exp((double)d3), h);
        float x1 = __fsub_rn(pcx, __fmul_rn(0.5f, pw));
        float y1 = __fsub_rn(pcy, __fmul_rn(0.5f, ph));
        float x2 = __fadd_rn(pcx, __fmul_rn(0.5f, pw));
        float y2 = __fadd_rn(pcy, __fmul_rn(0.5f, ph));
        float hmax = __fsub_rn(im_info[b * 3 + 0], 1.0f);
        float wmax = __fsub_rn(im_info[b * 3 + 1], 1.0f);
        x1 = fminf(fmaxf(x1, 0.0f), wmax);
        y1 = fminf(fmaxf(y1, 0.0f), hmax);
        x2 = fminf(fmaxf(x2, 0.0f), wmax);
        y2 = fminf(fmaxf(y2, 0.0f), hmax);
        bx1[tid] = x1; by1[tid] = y1; bx2[tid] = x2; by2[tid] = y2;
        barea[tid] = __fmul_rn(__fadd_rn(__fsub_rn(x2, x1), 1.0f),
                               __fadd_rn(__fsub_rn(y2, y1), 1.0f));
    }
    __syncthreads();

    /* ---- IoU suppression bitmasks: mask[i] bit j set iff j>i && iou>0.3 ---- */
    for (int item = tid; item < PRE_NMS_K * MW; item += NTHREADS) {
        int i = item / MW, w = item % MW;
        unsigned long long bits = 0ull;
        if (i < L) {
            float xi1 = bx1[i], yi1 = by1[i], xi2 = bx2[i], yi2 = by2[i], ai = barea[i];
            int j0 = w * 64;
            int jend = (j0 + 64 < L) ? j0 + 64 : L;
            for (int j = (j0 > i + 1 ? j0 : i + 1); j < jend; j++) {
                float xx1 = fmaxf(xi1, bx1[j]);
                float yy1 = fmaxf(yi1, by1[j]);
                float xx2 = fminf(xi2, bx2[j]);
                float yy2 = fminf(yi2, by2[j]);
                float iw = fmaxf(__fadd_rn(__fsub_rn(xx2, xx1), 1.0f), 0.0f);
                float ih = fmaxf(__fadd_rn(__fsub_rn(yy2, yy1), 1.0f), 0.0f);
                float inter = __fmul_rn(iw, ih);
                float uni = __fsub_rn(__fadd_rn(ai, barea[j]), inter);
                float iou = __fdiv_rn(inter, uni);
                if (iou > 0.3f) bits |= 1ull << (j - j0);
            }
        }
        maskA[item] = bits;
    }
    __syncthreads();

    /* ---- Serial greedy NMS over bitmasks (thread 0) ---- */
    if (tid == 0) {
        unsigned long long r[MW] = {0ull, 0ull, 0ull, 0ull, 0ull};
#pragma unroll
        for (int w = 0; w < MW; w++) {
            int i0w = w * 64;
            if (i0w < L) {
                int iend = (i0w + 64 < L) ? i0w + 64 : L;
                for (int c0 = i0w; c0 < iend; c0 += 16) {
                    int ce = (c0 + 16 < iend) ? c0 + 16 : iend;
                    unsigned long long mm[16];
#pragma unroll
                    for (int t = 0; t < 16; t++)
                        mm[t] = (c0 + t < ce) ? maskA[(c0 + t) * MW + w] : 0ull;
#pragma unroll
                    for (int t = 0; t < 16; t++) {
                        int i = c0 + t;
                        if (i < ce && !((r[w] >> (i - i0w)) & 1ull))
                            r[w] |= mm[t];
                    }
                }
                int nb = iend - i0w;
                unsigned long long vm = (nb >= 64) ? ~0ull : ((1ull << nb) - 1ull);
                unsigned long long kw = (~r[w]) & vm;
                while (kw) {
                    int t = __ffsll((long long)kw) - 1;
                    kw &= kw - 1ull;
                    const unsigned long long* m = maskA + (i0w + t) * MW;
#pragma unroll
                    for (int w2 = 0; w2 < MW; w2++)
                        if (w2 > w) r[w2] |= m[w2];
                }
            }
        }
#pragma unroll
        for (int w = 0; w < MW; w++) {
            int lo = w * 64;
            unsigned long long vm = (L <= lo) ? 0ull
                                  : ((L - lo >= 64) ? ~0ull : ((1ull << (L - lo)) - 1ull));
            keepw[w] = (~r[w]) & vm;
        }
    }
    __syncthreads();

    /* ---- Output: zero then scatter kept rows by rank ---- */
    float* outb = out + (size_t)b * (POST_KK * 5);
    for (int t = tid; t < POST_KK * 5; t += NTHREADS) outb[t] = 0.0f;
    __syncthreads();
    if (tid < L) {
        int w = tid >> 6, bp = tid & 63;
        if ((keepw[w] >> bp) & 1ull) {
            int rank = 0;
            for (int u = 0; u < w; u++) rank += __popcll(keepw[u]);
            rank += __popcll(keepw[w] & ((1ull << bp) - 1ull));
            if (rank < POST_KK) {
                float* row = outb + rank * 5;
                row[0] = (float)b;
                row[1] = bx1[tid];
                row[2] = by1[tid];
                row[3] = bx2[tid];
                row[4] = by2[tid];
            }
        }
    }
}

extern "C" void kernel_launch(void* const* d_in, const int* in_sizes, int n_in,
                              void* d_out, int out_size) {
    const float* cls_prob = (const float*)d_in[0];
    const float* boxes    = (const float*)d_in[1];
    const float* deltas   = (const float*)d_in[2];
    const float* im_info  = (const float*)d_in[3];
    int B = in_sizes[3] / 3;   /* im_info is (B,3) */
    cudaFuncSetAttribute(proposal_kernel,
                         cudaFuncAttributeMaxDynamicSharedMemorySize, SMEM_BYTES);
    proposal_kernel<<<B, NTHREADS, SMEM_BYTES>>>(cls_prob, boxes, deltas,
                                                 im_info, (float*)d_out);
}

// round 14
// speedup vs baseline: 1.7478x; 1.1690x over previous
#include <cuda_runtime.h>
#include <stdint.h>

#define NTHREADS 1024
#define NN 32768
#define NBINS 4096
#define PRE_NMS_K 300
#define POST_KK 100
#define CAND_CAP 4096
#define MW 5  /* ceil(300/64) */

/* ---- shared memory layout (bytes) ---- */
#define CAND_OFF   0                                /* raw s>=0.9 candidates */
#define CAND2_OFF  (CAND_OFF + CAND_CAP * 8)        /* 32768: selected */
#define HIST_OFF   (CAND2_OFF + CAND_CAP * 8)       /* 65536 */
#define BX1_OFF    (HIST_OFF + NBINS * 4)           /* 81920 */
#define BY1_OFF    (BX1_OFF + PRE_NMS_K * 4)
#define BX2_OFF    (BY1_OFF + PRE_NMS_K * 4)
#define BY2_OFF    (BX2_OFF + PRE_NMS_K * 4)
#define BAREA_OFF  (BY2_OFF + PRE_NMS_K * 4)
#define MASK_OFF   (BAREA_OFF + PRE_NMS_K * 4)      /* 87920, 8B aligned */
#define KEEP_OFF   (MASK_OFF + PRE_NMS_K * MW * 8)  /* 99920 */
#define WS_OFF     (KEEP_OFF + MW * 8)              /* 99960 */
#define SCAL_OFF   (WS_OFF + 32 * 4)
#define SMEM_BYTES (SCAL_OFF + 8 * 4)               /* ~100 KB */

__global__ void __launch_bounds__(NTHREADS, 1)
proposal_kernel(const float* __restrict__ cls_prob,
                const float* __restrict__ boxes,
                const float* __restrict__ deltas,
                const float* __restrict__ im_info,
                float* __restrict__ out)
{
    extern __shared__ unsigned char smem[];
    unsigned long long* cand  = (unsigned long long*)(smem + CAND_OFF);
    unsigned long long* cand2 = (unsigned long long*)(smem + CAND2_OFF);
    int*                hist  = (int*)(smem + HIST_OFF);
    float*              bx1   = (float*)(smem + BX1_OFF);
    float*              by1   = (float*)(smem + BY1_OFF);
    float*              bx2   = (float*)(smem + BX2_OFF);
    float*              by2   = (float*)(smem + BY2_OFF);
    float*              barea = (float*)(smem + BAREA_OFF);
    unsigned long long* maskA = (unsigned long long*)(smem + MASK_OFF);
    unsigned long long* keepw = (unsigned long long*)(smem + KEEP_OFF);
    int*                wsums = (int*)(smem + WS_OFF);
    int*                scal  = (int*)(smem + SCAL_OFF);
    /* scal: 0=cnt09(push), 1=bstar, 2=selCnt, 3=c005 */

    const int b    = blockIdx.x;
    const int tid  = threadIdx.x;
    const int lane = tid & 31;
    const int wrp  = tid >> 5;
    const unsigned lmlt = (1u << lane) - 1u;

    /* zero output early: overlaps STG with Phase A; later barriers order it
       against the final scatter */
    float* outb = out + (size_t)b * (POST_KK * 5);
    if (tid < POST_KK * 5) outb[tid] = 0.0f;

    for (int i = tid; i < NBINS; i += NTHREADS) hist[i] = 0;
    if (tid == 0) { scal[0] = 0; scal[1] = NBINS; scal[2] = 0; scal[3] = 0; }
    __syncthreads();

    /* ---- Phase A: stream scores, push s>=0.9 candidates (warp-aggregated) ---- */
    const float4* cp4 = (const float4*)(cls_prob + (size_t)b * (NN * 2));
    int c005 = 0;
#pragma unroll 8
    for (int k = 0; k < (NN / 2) / NTHREADS; k++) {      /* 16 iters */
        int m = tid + k * NTHREADS;
        float4 v = cp4[m];
        float s0 = v.y, s1 = v.w;        /* cls_prob[b, 2m, 1], [b, 2m+1, 1] */
        c005 += (s0 >= 0.05f) + (s1 >= 0.05f);
#pragma unroll
        for (int h = 0; h < 2; h++) {
            float s = h ? s1 : s0;
            bool p = (s >= 0.9f);
            unsigned bl = __ballot_sync(0xFFFFFFFFu, p);
            if (bl) {
                int base = 0;
                if (lane == 0) base = atomicAdd(&scal[0], __popc(bl));
                base = __shfl_sync(0xFFFFFFFFu, base, 0);
                if (p) {
                    int off = base + __popc(bl & lmlt);
                    if (off < CAND_CAP) {
                        int j = 2 * m + h;
                        cand[off] = ((unsigned long long)__float_as_uint(s) << 32) |
                                    (unsigned long long)(0xFFFFFFFFu - (uint32_t)j);
                    }
                }
            }
        }
    }
#pragma unroll
    for (int off = 16; off >= 1; off >>= 1)
        c005 += __shfl_down_sync(0xFFFFFFFFu, c005, off);
    if (lane == 0 && c005) atomicAdd(&scal[3], c005);
    __syncthreads();

    const int cnt09  = scal[0];
    const int cnt005 = scal[3];
    const int n09 = cnt09 < CAND_CAP ? cnt09 : CAND_CAP;
    const int target0 = cnt005 < PRE_NMS_K ? cnt005 : PRE_NMS_K;
    const bool fast = (cnt09 >= target0) && (cnt09 <= CAND_CAP);

    /* ---- histogram ---- */
    if (fast) {
        for (int i = tid; i < n09; i += NTHREADS) {
            float s = __uint_as_float((uint32_t)(cand[i] >> 32));
            int bin = (int)__fmul_rn(__fsub_rn(s, 0.9f), 40960.0f);
            bin = bin < NBINS - 1 ? bin : NBINS - 1;
            atomicAdd(&hist[bin], 1);
        }
    } else {
        const float2* cp = (const float2*)(cls_prob + (size_t)b * (NN * 2));
        for (int k = 0; k < NN / NTHREADS; k++) {
            int j = tid + k * NTHREADS;
            float s = cp[j].y;
            if (s >= 0.05f) {
                int bin = (int)__fmul_rn(__fsub_rn(s, 0.05f), (4096.0f / 0.95f));
                bin = bin < NBINS - 1 ? bin : NBINS - 1;
                atomicAdd(&hist[bin], 1);
            }
        }
    }
    __syncthreads();

    /* ---- chunk sums (top-down, 4 bins/thread) + shfl block scan -> bstar ---- */
    int base4 = NBINS - 4 * (tid + 1);
    int4 h0 = *(int4*)&hist[base4];
    int s4 = h0.x + h0.y + h0.z + h0.w;
    int v = s4;
#pragma unroll
    for (int off = 1; off < 32; off <<= 1) {
        int n = __shfl_up_sync(0xFFFFFFFFu, v, off);
        if (lane >= off) v += n;
    }
    if (lane == 31) wsums[wrp] = v;
    __syncthreads();
    if (wrp == 0) {
        int t = wsums[lane];
#pragma unroll
        for (int off = 1; off < 32; off <<= 1) {
            int n = __shfl_up_sync(0xFFFFFFFFu, t, off);
            if (lane >= off) t += n;
        }
        wsums[lane] = t;
    }
    __syncthreads();
    int inc = v + (wrp > 0 ? wsums[wrp - 1] : 0);
    int total = wsums[31];
    int target = total < PRE_NMS_K ? total : PRE_NMS_K;
    {
        int exc = inc - s4;
        if (target > 0 && exc < target && target <= inc) {
            int cum = exc, bsel = base4;
            for (int u = 3; u >= 0; u--) {
                cum += hist[base4 + u];
                if (cum >= target) { bsel = base4 + u; break; }
            }
            scal[1] = bsel;
        }
    }
    __syncthreads();
    int bstar = scal[1];

    /* ---- compact selected candidates into cand2 ---- */
    if (fast) {
        for (int i = tid; i < n09; i += NTHREADS) {
            unsigned long long kk = cand[i];
            float s = __uint_as_float((uint32_t)(kk >> 32));
            int bin = (int)__fmul_rn(__fsub_rn(s, 0.9f), 40960.0f);
            bin = bin < NBINS - 1 ? bin : NBINS - 1;
            if (bin >= bstar) {
                int p = atomicAdd(&scal[2], 1);
                if (p < CAND_CAP) cand2[p] = kk;
            }
        }
    } else {
        const float2* cp = (const float2*)(cls_prob + (size_t)b * (NN * 2));
        for (int k = 0; k < NN / NTHREADS; k++) {
            int j = tid + k * NTHREADS;
            float s = cp[j].y;
            if (s >= 0.05f) {
                int bin = (int)__fmul_rn(__fsub_rn(s, 0.05f), (4096.0f / 0.95f));
                bin = bin < NBINS - 1 ? bin : NBINS - 1;
                if (bin >= bstar) {
                    int p = atomicAdd(&scal[2], 1);
                    if (p < CAND_CAP)
                        cand2[p] = ((unsigned long long)__float_as_uint(s) << 32) |
                                   (unsigned long long)(0xFFFFFFFFu - (uint32_t)j);
                }
            }
        }
    }
    __syncthreads();
    int cnt = scal[2] < CAND_CAP ? scal[2] : CAND_CAP;
    int M = 512;
    while (M < cnt) M <<= 1;
    for (int i = cnt + tid; i < M; i += NTHREADS) cand2[i] = 0ull;
    __syncthreads();

    /* ---- Bitonic sort descending: (score desc, idx asc) == jax top_k order.
            M==512 path: threads >=512 harmlessly run the same network on
            cand2[512..1024) garbage (tid^jj stays in the same half). ---- */
    if (M == 512) {
        unsigned long long a = cand2[tid];
#pragma unroll
        for (int k2 = 2; k2 <= 32; k2 <<= 1) {
#pragma unroll
            for (int jj = 16; jj >= 1; jj >>= 1) {
                if (jj <= (k2 >> 1)) {
                    unsigned long long c = __shfl_xor_sync(0xFFFFFFFFu, a, jj);
                    bool keepmax = (((tid & k2) == 0) == ((tid & jj) == 0));
                    unsigned long long mx = a > c ? a : c;
                    unsigned long long mn = a > c ? c : a;
                    a = keepmax ? mx : mn;
                }
            }
        }
        cand2[tid] = a;
        __syncthreads();
        for (int k2 = 64; k2 <= 512; k2 <<= 1) {
            for (int jj = k2 >> 1; jj >= 32; jj >>= 1) {
                int l = tid ^ jj;
                if (l > tid) {
                    unsigned long long x = cand2[tid];
                    unsigned long long y = cand2[l];
                    bool up = ((tid & k2) == 0);
                    if (up ? (x < y) : (x > y)) { cand2[tid] = y; cand2[l] = x; }
                }
                __syncthreads();
            }
            a = cand2[tid];
#pragma unroll
            for (int jj = 16; jj >= 1; jj >>= 1) {
                unsigned long long c = __shfl_xor_sync(0xFFFFFFFFu, a, jj);
                bool keepmax = (((tid & k2) == 0) == ((tid & jj) == 0));
                unsigned long long mx = a > c ? a : c;
                unsigned long long mn = a > c ? c : a;
                a = keepmax ? mx : mn;
            }
            cand2[tid] = a;
            __syncthreads();
        }
    } else {
        for (int k2 = 2; k2 <= M; k2 <<= 1) {
            for (int jj = k2 >> 1; jj > 0; jj >>= 1) {
                for (int i = tid; i < M; i += NTHREADS) {
                    int l = i ^ jj;
                    if (l > i) {
                        unsigned long long a2 = cand2[i];
                        unsigned long long c2 = cand2[l];
                        bool up = ((i & k2) == 0);
                        if (up ? (a2 < c2) : (a2 > c2)) { cand2[i] = c2; cand2[l] = a2; }
                    }
                }
                __syncthreads();
            }
        }
    }

    int L = cnt < PRE_NMS_K ? cnt : PRE_NMS_K;

    /* ---- Decode + clip selected boxes (rn intrinsics: no FMA contraction) ---- */
    if (tid < L) {
        unsigned long long kk = cand2[tid];
        int j = (int)(0xFFFFFFFFu - (uint32_t)(kk & 0xFFFFFFFFull));
        float4 bb = *(const float4*)(boxes  + ((size_t)b * NN + j) * 4);
        float4 dd = *(const float4*)(deltas + ((size_t)b * NN + j) * 4);
        float w  = __fadd_rn(__fsub_rn(bb.z, bb.x), 1.0f);
        float h  = __fadd_rn(__fsub_rn(bb.w, bb.y), 1.0f);
        float cx = __fadd_rn(bb.x, __fmul_rn(0.5f, w));
        float cy = __fadd_rn(bb.y, __fmul_rn(0.5f, h));
        float d0 = __fmul_rn(dd.x, 0.1f);
        float d1 = __fmul_rn(dd.y, 0.1f);
        float d2 = __fmul_rn(dd.z, 0.2f);
        float d3 = __fmul_rn(dd.w, 0.2f);
        float pcx = __fadd_rn(__fmul_rn(d0, w), cx);
        float pcy = __fadd_rn(__fmul_rn(d1, h), cy);
        float pw  = __fmul_rn((float)exp((double)d2), w);
        float ph  = __fmul_rn((float)exp((double)d3), h);
        float x1 = __fsub_rn(pcx, __fmul_rn(0.5f, pw));
        float y1 = __fsub_rn(pcy, __fmul_rn(0.5f, ph));
        float x2 = __fadd_rn(pcx, __fmul_rn(0.5f, pw));
        float y2 = __fadd_rn(pcy, __fmul_rn(0.5f, ph));
        float hmax = __fsub_rn(im_info[b * 3 + 0], 1.0f);
        float wmax = __fsub_rn(im_info[b * 3 + 1], 1.0f);
        x1 = fminf(fmaxf(x1, 0.0f), wmax);
        y1 = fminf(fmaxf(y1, 0.0f), hmax);
        x2 = fminf(fmaxf(x2, 0.0f), wmax);
        y2 = fminf(fmaxf(y2, 0.0f), hmax);
        bx1[tid] = x1; by1[tid] = y1; bx2[tid] = x2; by2[tid] = y2;
        barea[tid] = __fmul_rn(__fadd_rn(__fsub_rn(x2, x1), 1.0f),
                               __fadd_rn(__fsub_rn(y2, y1), 1.0f));
    }
    __syncthreads();

    /* ---- IoU suppression bitmasks: mask[i] bit j set iff j>i && iou>0.3 ---- */
    for (int item = tid; item < PRE_NMS_K * MW; item += NTHREADS) {
        int i = item / MW, w = item % MW;
        unsigned long long bits = 0ull;
        if (i < L) {
            float xi1 = bx1[i], yi1 = by1[i], xi2 = bx2[i], yi2 = by2[i], ai = barea[i];
            int j0 = w * 64;
            int jend = (j0 + 64 < L) ? j0 + 64 : L;
            for (int j = (j0 > i + 1 ? j0 : i + 1); j < jend; j++) {
                float xx1 = fmaxf(xi1, bx1[j]);
                float yy1 = fmaxf(yi1, by1[j]);
                float xx2 = fminf(xi2, bx2[j]);
                float yy2 = fminf(yi2, by2[j]);
                float iw = fmaxf(__fadd_rn(__fsub_rn(xx2, xx1), 1.0f), 0.0f);
                float ih = fmaxf(__fadd_rn(__fsub_rn(yy2, yy1), 1.0f), 0.0f);
                float inter = __fmul_rn(iw, ih);
                float uni = __fsub_rn(__fadd_rn(ai, barea[j]), inter);
                float iou = __fdiv_rn(inter, uni);
                if (iou > 0.3f) bits |= 1ull << (j - j0);
            }
        }
        maskA[item] = bits;
    }
    __syncthreads();

    /* ---- Serial greedy NMS over bitmasks (thread 0) ---- */
    if (tid == 0) {
        unsigned long long r[MW] = {0ull, 0ull, 0ull, 0ull, 0ull};
#pragma unroll
        for (int w = 0; w < MW; w++) {
            int i0w = w * 64;
            if (i0w < L) {
                int iend = (i0w + 64 < L) ? i0w + 64 : L;
                for (int c0 = i0w; c0 < iend; c0 += 16) {
                    int ce = (c0 + 16 < iend) ? c0 + 16 : iend;
                    unsigned long long mm[16];
#pragma unroll
                    for (int t = 0; t < 16; t++)
                        mm[t] = (c0 + t < ce) ? maskA[(c0 + t) * MW + w] : 0ull;
#pragma unroll
                    for (int t = 0; t < 16; t++) {
                        int i = c0 + t;
                        if (i < ce && !((r[w] >> (i - i0w)) & 1ull))
                            r[w] |= mm[t];
                    }
                }
                int nb = iend - i0w;
                unsigned long long vm = (nb >= 64) ? ~0ull : ((1ull << nb) - 1ull);
                unsigned long long kw = (~r[w]) & vm;
                while (kw) {
                    int t = __ffsll((long long)kw) - 1;
                    kw &= kw - 1ull;
                    const unsigned long long* m = maskA + (i0w + t) * MW;
#pragma unroll
                    for (int w2 = 0; w2 < MW; w2++)
                        if (w2 > w) r[w2] |= m[w2];
                }
            }
        }
#pragma unroll
        for (int w = 0; w < MW; w++) {
            int lo = w * 64;
            unsigned long long vm = (L <= lo) ? 0ull
                                  : ((L - lo >= 64) ? ~0ull : ((1ull << (L - lo)) - 1ull));
            keepw[w] = (~r[w]) & vm;
        }
    }
    __syncthreads();

    /* ---- Output: scatter kept rows by rank (out already zeroed at start) ---- */
    if (tid < L) {
        int w = tid >> 6, bp = tid & 63;
        if ((keepw[w] >> bp) & 1ull) {
            int rank = 0;
            for (int u = 0; u < w; u++) rank += __popcll(keepw[u]);
            rank += __popcll(keepw[w] & ((1ull << bp) - 1ull));
            if (rank < POST_KK) {
                float* row = outb + rank * 5;
                row[0] = (float)b;
                row[1] = bx1[tid];
                row[2] = by1[tid];
                row[3] = bx2[tid];
                row[4] = by2[tid];
            }
        }
    }
}

extern "C" void kernel_launch(void* const* d_in, const int* in_sizes, int n_in,
                              void* d_out, int out_size) {
    const float* cls_prob = (const float*)d_in[0];
    const float* boxes    = (const float*)d_in[1];
    const float* deltas   = (const float*)d_in[2];
    const float* im_info  = (const float*)d_in[3];
    int B = in_sizes[3] / 3;   /* im_info is (B,3) */
    cudaFuncSetAttribute(proposal_kernel,
                         cudaFuncAttributeMaxDynamicSharedMemorySize, SMEM_BYTES);
    proposal_kernel<<<B, NTHREADS, SMEM_BYTES>>>(cls_prob, boxes, deltas,
                                                 im_info, (float*)d_out);
}

// round 16
// speedup vs baseline: 1.7607x; 1.0074x over previous
#include <cuda_runtime.h>
#include <stdint.h>

#define NTHREADS 1024
#define NN 32768
#define NBINS 4096
#define PRE_NMS_K 300
#define POST_KK 100
#define CAND_CAP 4096
#define MW 5  /* ceil(300/64) */
#define NPAIR ((PRE_NMS_K + 1) / 2)   /* 150 i-pairs */

/* ---- shared memory layout (bytes) ---- */
#define CAND_OFF   0                                /* raw s>=0.9 candidates */
#define CAND2_OFF  (CAND_OFF + CAND_CAP * 8)        /* 32768: selected */
#define HIST_OFF   (CAND2_OFF + CAND_CAP * 8)       /* 65536 */
#define BQ_OFF     (HIST_OFF + NBINS * 4)           /* 81920: float4 boxes */
#define BAREA_OFF  (BQ_OFF + PRE_NMS_K * 16)        /* 86720 */
#define MASK_OFF   (BAREA_OFF + PRE_NMS_K * 4)      /* 87920, 8B aligned */
#define KEEP_OFF   (MASK_OFF + PRE_NMS_K * MW * 8)  /* 99920 */
#define WS_OFF     (KEEP_OFF + MW * 8)              /* 99960 */
#define SCAL_OFF   (WS_OFF + 32 * 4)
#define SMEM_BYTES (SCAL_OFF + 8 * 4)               /* ~100 KB */

__global__ void __launch_bounds__(NTHREADS, 1)
proposal_kernel(const float* __restrict__ cls_prob,
                const float* __restrict__ boxes,
                const float* __restrict__ deltas,
                const float* __restrict__ im_info,
                float* __restrict__ out)
{
    extern __shared__ unsigned char smem[];
    unsigned long long* cand  = (unsigned long long*)(smem + CAND_OFF);
    unsigned long long* cand2 = (unsigned long long*)(smem + CAND2_OFF);
    int*                hist  = (int*)(smem + HIST_OFF);
    float4*             bq    = (float4*)(smem + BQ_OFF);
    float*              barea = (float*)(smem + BAREA_OFF);
    unsigned long long* maskA = (unsigned long long*)(smem + MASK_OFF);
    unsigned long long* keepw = (unsigned long long*)(smem + KEEP_OFF);
    int*                wsums = (int*)(smem + WS_OFF);
    int*                scal  = (int*)(smem + SCAL_OFF);
    /* scal: 0=cnt09(push), 1=bstar, 2=selCnt */

    const int b    = blockIdx.x;
    const int tid  = threadIdx.x;
    const int lane = tid & 31;
    const int wrp  = tid >> 5;
    const unsigned lmlt = (1u << lane) - 1u;

    /* zero output early (overlaps with Phase A; barriers order vs final scatter) */
    float* outb = out + (size_t)b * (POST_KK * 5);
    if (tid < POST_KK * 5) outb[tid] = 0.0f;

    for (int i = tid; i < NBINS; i += NTHREADS) hist[i] = 0;
    if (tid == 0) { scal[0] = 0; scal[1] = NBINS; scal[2] = 0; }
    __syncthreads();

    /* ---- Phase A: stream scores, push s>=0.9 candidates
            (one warp-aggregated atomic per iteration) ---- */
    const float4* cp4 = (const float4*)(cls_prob + (size_t)b * (NN * 2));
#pragma unroll 8
    for (int k = 0; k < (NN / 2) / NTHREADS; k++) {      /* 16 iters */
        int m = tid + k * NTHREADS;
        float4 v = cp4[m];
        float s0 = v.y, s1 = v.w;        /* cls_prob[b, 2m, 1], [b, 2m+1, 1] */
        bool p0 = (s0 >= 0.9f);
        bool p1 = (s1 >= 0.9f);
        unsigned b0 = __ballot_sync(0xFFFFFFFFu, p0);
        unsigned b1 = __ballot_sync(0xFFFFFFFFu, p1);
        if (b0 | b1) {
            int tot = __popc(b0) + __popc(b1);
            int base = 0;
            if (lane == 0) base = atomicAdd(&scal[0], tot);
            base = __shfl_sync(0xFFFFFFFFu, base, 0);
            if (p0) {
                int off = base + __popc(b0 & lmlt);
                if (off < CAND_CAP) {
                    int j = 2 * m;
                    cand[off] = ((unsigned long long)__float_as_uint(s0) << 32) |
                                (unsigned long long)(0xFFFFFFFFu - (uint32_t)j);
                }
            }
            if (p1) {
                int off = base + __popc(b0) + __popc(b1 & lmlt);
                if (off < CAND_CAP) {
                    int j = 2 * m + 1;
                    cand[off] = ((unsigned long long)__float_as_uint(s1) << 32) |
                                (unsigned long long)(0xFFFFFFFFu - (uint32_t)j);
                }
            }
        }
    }
    __syncthreads();

    const int cnt09 = scal[0];
    const int n09 = cnt09 < CAND_CAP ? cnt09 : CAND_CAP;
    /* if cnt09 < 300, the overall top-300 may include s<0.9 items -> exact
       fallback (full-range histogram) handles it; its own total gives target */
    const bool fast = (cnt09 >= PRE_NMS_K) && (cnt09 <= CAND_CAP);

    /* ---- histogram ---- */
    if (fast) {
        for (int i = tid; i < n09; i += NTHREADS) {
            float s = __uint_as_float((uint32_t)(cand[i] >> 32));
            int bin = (int)__fmul_rn(__fsub_rn(s, 0.9f), 40960.0f);
            bin = bin < NBINS - 1 ? bin : NBINS - 1;
            atomicAdd(&hist[bin], 1);
        }
    } else {
        const float2* cp = (const float2*)(cls_prob + (size_t)b * (NN * 2));
        for (int k = 0; k < NN / NTHREADS; k++) {
            int j = tid + k * NTHREADS;
            float s = cp[j].y;
            if (s >= 0.05f) {
                int bin = (int)__fmul_rn(__fsub_rn(s, 0.05f), (4096.0f / 0.95f));
                bin = bin < NBINS - 1 ? bin : NBINS - 1;
                atomicAdd(&hist[bin], 1);
            }
        }
    }
    __syncthreads();

    /* ---- chunk sums (top-down, 4 bins/thread) + shfl block scan -> bstar ---- */
    int base4 = NBINS - 4 * (tid + 1);
    int4 h0 = *(int4*)&hist[base4];
    int s4 = h0.x + h0.y + h0.z + h0.w;
    int v = s4;
#pragma unroll
    for (int off = 1; off < 32; off <<= 1) {
        int n = __shfl_up_sync(0xFFFFFFFFu, v, off);
        if (lane >= off) v += n;
    }
    if (lane == 31) wsums[wrp] = v;
    __syncthreads();
    if (wrp == 0) {
        int t = wsums[lane];
#pragma unroll
        for (int off = 1; off < 32; off <<= 1) {
            int n = __shfl_up_sync(0xFFFFFFFFu, t, off);
            if (lane >= off) t += n;
        }
        wsums[lane] = t;
    }
    __syncthreads();
    int inc = v + (wrp > 0 ? wsums[wrp - 1] : 0);
    int total = wsums[31];
    int target = total < PRE_NMS_K ? total : PRE_NMS_K;
    {
        int exc = inc - s4;
        if (target > 0 && exc < target && target <= inc) {
            int cum = exc, bsel = base4;
            for (int u = 3; u >= 0; u--) {
                cum += hist[base4 + u];
                if (cum >= target) { bsel = base4 + u; break; }
            }
            scal[1] = bsel;
        }
    }
    __syncthreads();
    int bstar = scal[1];

    /* ---- compact selected candidates into cand2 ---- */
    if (fast) {
        for (int i = tid; i < n09; i += NTHREADS) {
            unsigned long long kk = cand[i];
            float s = __uint_as_float((uint32_t)(kk >> 32));
            int bin = (int)__fmul_rn(__fsub_rn(s, 0.9f), 40960.0f);
            bin = bin < NBINS - 1 ? bin : NBINS - 1;
            if (bin >= bstar) {
                int p = atomicAdd(&scal[2], 1);
                if (p < CAND_CAP) cand2[p] = kk;
            }
        }
    } else {
        const float2* cp = (const float2*)(cls_prob + (size_t)b * (NN * 2));
        for (int k = 0; k < NN / NTHREADS; k++) {
            int j = tid + k * NTHREADS;
            float s = cp[j].y;
            if (s >= 0.05f) {
                int bin = (int)__fmul_rn(__fsub_rn(s, 0.05f), (4096.0f / 0.95f));
                bin = bin < NBINS - 1 ? bin : NBINS - 1;
                if (bin >= bstar) {
                    int p = atomicAdd(&scal[2], 1);
                    if (p < CAND_CAP)
                        cand2[p] = ((unsigned long long)__float_as_uint(s) << 32) |
                                   (unsigned long long)(0xFFFFFFFFu - (uint32_t)j);
                }
            }
        }
    }
    __syncthreads();
    int cnt = scal[2] < CAND_CAP ? scal[2] : CAND_CAP;
    int M = 512;
    while (M < cnt) M <<= 1;
    for (int i = cnt + tid; i < M; i += NTHREADS) cand2[i] = 0ull;
    __syncthreads();

    /* ---- Bitonic sort descending: (score desc, idx asc) == jax top_k order.
            M==512: threads >=512 run the network on cand2[512..1024) garbage
            harmlessly (tid^jj stays in the same half). ---- */
    if (M == 512) {
        unsigned long long a = cand2[tid];
#pragma unroll
        for (int k2 = 2; k2 <= 32; k2 <<= 1) {
#pragma unroll
            for (int jj = 16; jj >= 1; jj >>= 1) {
                if (jj <= (k2 >> 1)) {
                    unsigned long long c = __shfl_xor_sync(0xFFFFFFFFu, a, jj);
                    bool keepmax = (((tid & k2) == 0) == ((tid & jj) == 0));
                    unsigned long long mx = a > c ? a : c;
                    unsigned long long mn = a > c ? c : a;
                    a = keepmax ? mx : mn;
                }
            }
        }
        cand2[tid] = a;
        __syncthreads();
        for (int k2 = 64; k2 <= 512; k2 <<= 1) {
            for (int jj = k2 >> 1; jj >= 32; jj >>= 1) {
                int l = tid ^ jj;
                if (l > tid) {
                    unsigned long long x = cand2[tid];
                    unsigned long long y = cand2[l];
                    bool up = ((tid & k2) == 0);
                    if (up ? (x < y) : (x > y)) { cand2[tid] = y; cand2[l] = x; }
                }
                __syncthreads();
            }
            a = cand2[tid];
#pragma unroll
            for (int jj = 16; jj >= 1; jj >>= 1) {
                unsigned long long c = __shfl_xor_sync(0xFFFFFFFFu, a, jj);
                bool keepmax = (((tid & k2) == 0) == ((tid & jj) == 0));
                unsigned long long mx = a > c ? a : c;
                unsigned long long mn = a > c ? c : a;
                a = keepmax ? mx : mn;
            }
            cand2[tid] = a;
            __syncthreads();
        }
    } else {
        for (int k2 = 2; k2 <= M; k2 <<= 1) {
            for (int jj = k2 >> 1; jj > 0; jj >>= 1) {
                for (int i = tid; i < M; i += NTHREADS) {
                    int l = i ^ jj;
                    if (l > i) {
                        unsigned long long a2 = cand2[i];
                        unsigned long long c2 = cand2[l];
                        bool up = ((i & k2) == 0);
                        if (up ? (a2 < c2) : (a2 > c2)) { cand2[i] = c2; cand2[l] = a2; }
                    }
                }
                __syncthreads();
            }
        }
    }

    int L = cnt < PRE_NMS_K ? cnt : PRE_NMS_K;

    /* ---- Decode + clip selected boxes (rn intrinsics: no FMA contraction) ---- */
    if (tid < L) {
        unsigned long long kk = cand2[tid];
        int j = (int)(0xFFFFFFFFu - (uint32_t)(kk & 0xFFFFFFFFull));
        float4 bb = *(const float4*)(boxes  + ((size_t)b * NN + j) * 4);
        float4 dd = *(const float4*)(deltas + ((size_t)b * NN + j) * 4);
        float w  = __fadd_rn(__fsub_rn(bb.z, bb.x), 1.0f);
        float h  = __fadd_rn(__fsub_rn(bb.w, bb.y), 1.0f);
        float cx = __fadd_rn(bb.x, __fmul_rn(0.5f, w));
        float cy = __fadd_rn(bb.y, __fmul_rn(0.5f, h));
        float d0 = __fmul_rn(dd.x, 0.1f);
        float d1 = __fmul_rn(dd.y, 0.1f);
        float d2 = __fmul_rn(dd.z, 0.2f);
        float d3 = __fmul_rn(dd.w, 0.2f);
        float pcx = __fadd_rn(__fmul_rn(d0, w), cx);
        float pcy = __fadd_rn(__fmul_rn(d1, h), cy);
        float pw  = __fmul_rn((float)exp((double)d2), w);
        float ph  = __fmul_rn((float)exp((double)d3), h);
        float x1 = __fsub_rn(pcx, __fmul_rn(0.5f, pw));
        float y1 = __fsub_rn(pcy, __fmul_rn(0.5f, ph));
        float x2 = __fadd_rn(pcx, __fmul_rn(0.5f, pw));
        float y2 = __fadd_rn(pcy, __fmul_rn(0.5f, ph));
        float hmax = __fsub_rn(im_info[b * 3 + 0], 1.0f);
        float wmax = __fsub_rn(im_info[b * 3 + 1], 1.0f);
        x1 = fminf(fmaxf(x1, 0.0f), wmax);
        y1 = fminf(fmaxf(y1, 0.0f), hmax);
        x2 = fminf(fmaxf(x2, 0.0f), wmax);
        y2 = fminf(fmaxf(y2, 0.0f), hmax);
        bq[tid] = make_float4(x1, y1, x2, y2);
        barea[tid] = __fmul_rn(__fadd_rn(__fsub_rn(x2, x1), 1.0f),
                               __fadd_rn(__fsub_rn(y2, y1), 1.0f));
    }
    __syncthreads();

    /* ---- IoU suppression bitmasks (paired i-rows share j loads):
            mask[i] bit j set iff j>i && iou>0.3 ---- */
    for (int item = tid; item < NPAIR * MW; item += NTHREADS) {   /* 750 items */
        int ip = item / MW, w = item % MW;
        int i0 = 2 * ip, i1 = i0 + 1;
        if (i0 >= L) continue;
        float4 q0 = bq[i0];
        float  a0 = barea[i0];
        bool   has1 = (i1 < L);
        float4 q1 = has1 ? bq[i1] : q0;
        float  a1 = has1 ? barea[i1] : a0;
        unsigned long long bits0 = 0ull, bits1 = 0ull;
        int j0 = w * 64;
        int jend = (j0 + 64 < L) ? j0 + 64 : L;
        int jst = (j0 > i0 + 1) ? j0 : i0 + 1;
        for (int j = jst; j < jend; j++) {
            float4 qj = bq[j];
            float  aj = barea[j];
            /* vs i0 */
            {
                float xx1 = fmaxf(q0.x, qj.x);
                float yy1 = fmaxf(q0.y, qj.y);
                float xx2 = fminf(q0.z, qj.z);
                float yy2 = fminf(q0.w, qj.w);
                float iw = fmaxf(__fadd_rn(__fsub_rn(xx2, xx1), 1.0f), 0.0f);
                float ih = fmaxf(__fadd_rn(__fsub_rn(yy2, yy1), 1.0f), 0.0f);
                float inter = __fmul_rn(iw, ih);
                float uni = __fsub_rn(__fadd_rn(a0, aj), inter);
                float iou = __fdiv_rn(inter, uni);
                if ((j > i0) && (iou > 0.3f)) bits0 |= 1ull << (j - j0);
            }
            /* vs i1 */
            if (has1) {
                float xx1 = fmaxf(q1.x, qj.x);
                float yy1 = fmaxf(q1.y, qj.y);
                float xx2 = fminf(q1.z, qj.z);
                float yy2 = fminf(q1.w, qj.w);
                float iw = fmaxf(__fadd_rn(__fsub_rn(xx2, xx1), 1.0f), 0.0f);
                float ih = fmaxf(__fadd_rn(__fsub_rn(yy2, yy1), 1.0f), 0.0f);
                float inter = __fmul_rn(iw, ih);
                float uni = __fsub_rn(__fadd_rn(a1, aj), inter);
                float iou = __fdiv_rn(inter, uni);
                if ((j > i1) && (iou > 0.3f)) bits1 |= 1ull << (j - j0);
            }
        }
        maskA[i0 * MW + w] = bits0;
        if (has1) maskA[i1 * MW + w] = bits1;
    }
    __syncthreads();

    /* ---- Serial greedy NMS over bitmasks (thread 0) ---- */
    if (tid == 0) {
        unsigned long long r[MW] = {0ull, 0ull, 0ull, 0ull, 0ull};
#pragma unroll
        for (int w = 0; w < MW; w++) {
            int i0w = w * 64;
            if (i0w < L) {
                int iend = (i0w + 64 < L) ? i0w + 64 : L;
                for (int c0 = i0w; c0 < iend; c0 += 16) {
                    int ce = (c0 + 16 < iend) ? c0 + 16 : iend;
                    unsigned long long mm[16];
#pragma unroll
                    for (int t = 0; t < 16; t++)
                        mm[t] = (c0 + t < ce) ? maskA[(c0 + t) * MW + w] : 0ull;
#pragma unroll
                    for (int t = 0; t < 16; t++) {
                        int i = c0 + t;
                        if (i < ce && !((r[w] >> (i - i0w)) & 1ull))
                            r[w] |= mm[t];
                    }
                }
                int nb = iend - i0w;
                unsigned long long vm = (nb >= 64) ? ~0ull : ((1ull << nb) - 1ull);
                unsigned long long kw = (~r[w]) & vm;
                while (kw) {
                    int t = __ffsll((long long)kw) - 1;
                    kw &= kw - 1ull;
                    const unsigned long long* m = maskA + (i0w + t) * MW;
#pragma unroll
                    for (int w2 = 0; w2 < MW; w2++)
                        if (w2 > w) r[w2] |= m[w2];
                }
            }
        }
#pragma unroll
        for (int w = 0; w < MW; w++) {
            int lo = w * 64;
            unsigned long long vm = (L <= lo) ? 0ull
                                  : ((L - lo >= 64) ? ~0ull : ((1ull << (L - lo)) - 1ull));
            keepw[w] = (~r[w]) & vm;
        }
    }
    __syncthreads();

    /* ---- Output: scatter kept rows by rank (out already zeroed at start) ---- */
    if (tid < L) {
        int w = tid >> 6, bp = tid & 63;
        if ((keepw[w] >> bp) & 1ull) {
            int rank = 0;
            for (int u = 0; u < w; u++) rank += __popcll(keepw[u]);
            rank += __popcll(keepw[w] & ((1ull << bp) - 1ull));
            if (rank < POST_KK) {
                float4 q = bq[tid];
                float* row = outb + rank * 5;
                row[0] = (float)b;
                row[1] = q.x;
                row[2] = q.y;
                row[3] = q.z;
                row[4] = q.w;
            }
        }
    }
}

extern "C" void kernel_launch(void* const* d_in, const int* in_sizes, int n_in,
                              void* d_out, int out_size) {
    const float* cls_prob = (const float*)d_in[0];
    const float* boxes    = (const float*)d_in[1];
    const float* deltas   = (const float*)d_in[2];
    const float* im_info  = (const float*)d_in[3];
    int B = in_sizes[3] / 3;   /* im_info is (B,3) */
    cudaFuncSetAttribute(proposal_kernel,
                         cudaFuncAttributeMaxDynamicSharedMemorySize, SMEM_BYTES);
    proposal_kernel<<<B, NTHREADS, SMEM_BYTES>>>(cls_prob, boxes, deltas,
                                                 im_info, (float*)d_out);
}

// round 17
// speedup vs baseline: 1.8499x; 1.0506x over previous
#include <cuda_runtime.h>
#include <stdint.h>

#define NTHREADS 1024
#define NN 32768
#define NBINS 4096
#define PRE_NMS_K 300
#define POST_KK 100
#define CAND_CAP 4096
#define MW 5  /* ceil(300/64) */
#define NPAIR ((PRE_NMS_K + 1) / 2)   /* 150 i-pairs */

/* ---- shared memory layout (bytes) ---- */
#define CAND_OFF   0                                /* raw s>=0.9 candidates */
#define CAND2_OFF  (CAND_OFF + CAND_CAP * 8)        /* 32768: rank-ordered */
#define HIST_OFF   (CAND2_OFF + CAND_CAP * 8)       /* 65536 */
#define RANKB_OFF  (HIST_OFF + NBINS * 4)           /* 81920: suffix offsets */
#define BQ_OFF     (RANKB_OFF + NBINS * 4)          /* 98304: float4 boxes */
#define BAREA_OFF  (BQ_OFF + PRE_NMS_K * 16)        /* 103104 */
#define MASK_OFF   (BAREA_OFF + PRE_NMS_K * 4)      /* 104304, 8B aligned */
#define KEEP_OFF   (MASK_OFF + PRE_NMS_K * MW * 8)  /* 116304 */
#define WS_OFF     (KEEP_OFF + MW * 8)              /* 116344 */
#define SCAL_OFF   (WS_OFF + 32 * 4)                /* 116472 */
#define SMEM_BYTES (SCAL_OFF + 8 * 4)               /* ~114 KB */

__global__ void __launch_bounds__(NTHREADS, 1)
proposal_kernel(const float* __restrict__ cls_prob,
                const float* __restrict__ boxes,
                const float* __restrict__ deltas,
                const float* __restrict__ im_info,
                float* __restrict__ out)
{
    extern __shared__ unsigned char smem[];
    unsigned long long* cand  = (unsigned long long*)(smem + CAND_OFF);
    unsigned long long* cand2 = (unsigned long long*)(smem + CAND2_OFF);
    int*                hist  = (int*)(smem + HIST_OFF);
    int*                rankb = (int*)(smem + RANKB_OFF);
    float4*             bq    = (float4*)(smem + BQ_OFF);
    float*              barea = (float*)(smem + BAREA_OFF);
    unsigned long long* maskA = (unsigned long long*)(smem + MASK_OFF);
    unsigned long long* keepw = (unsigned long long*)(smem + KEEP_OFF);
    int*                wsums = (int*)(smem + WS_OFF);
    int*                scal  = (int*)(smem + SCAL_OFF);
    /* scal: 0=cnt09(push), 1=bstar, 2=selCnt */

    const int b    = blockIdx.x;
    const int tid  = threadIdx.x;
    const int lane = tid & 31;
    const int wrp  = tid >> 5;
    const unsigned lmlt = (1u << lane) - 1u;

    /* zero output early (overlaps with Phase A; barriers order vs final scatter) */
    float* outb = out + (size_t)b * (POST_KK * 5);
    if (tid < POST_KK * 5) outb[tid] = 0.0f;

    for (int i = tid; i < NBINS; i += NTHREADS) hist[i] = 0;
    if (tid == 0) { scal[0] = 0; scal[1] = NBINS; scal[2] = 0; }
    __syncthreads();

    /* ---- Phase A: stream scores, push s>=0.9 candidates
            (one warp-aggregated atomic per iteration) ---- */
    const float4* cp4 = (const float4*)(cls_prob + (size_t)b * (NN * 2));
#pragma unroll 8
    for (int k = 0; k < (NN / 2) / NTHREADS; k++) {      /* 16 iters */
        int m = tid + k * NTHREADS;
        float4 v = cp4[m];
        float s0 = v.y, s1 = v.w;        /* cls_prob[b, 2m, 1], [b, 2m+1, 1] */
        bool p0 = (s0 >= 0.9f);
        bool p1 = (s1 >= 0.9f);
        unsigned b0 = __ballot_sync(0xFFFFFFFFu, p0);
        unsigned b1 = __ballot_sync(0xFFFFFFFFu, p1);
        if (b0 | b1) {
            int tot = __popc(b0) + __popc(b1);
            int base = 0;
            if (lane == 0) base = atomicAdd(&scal[0], tot);
            base = __shfl_sync(0xFFFFFFFFu, base, 0);
            if (p0) {
                int off = base + __popc(b0 & lmlt);
                if (off < CAND_CAP) {
                    int j = 2 * m;
                    cand[off] = ((unsigned long long)__float_as_uint(s0) << 32) |
                                (unsigned long long)(0xFFFFFFFFu - (uint32_t)j);
                }
            }
            if (p1) {
                int off = base + __popc(b0) + __popc(b1 & lmlt);
                if (off < CAND_CAP) {
                    int j = 2 * m + 1;
                    cand[off] = ((unsigned long long)__float_as_uint(s1) << 32) |
                                (unsigned long long)(0xFFFFFFFFu - (uint32_t)j);
                }
            }
        }
    }
    __syncthreads();

    const int cnt09 = scal[0];
    const int n09 = cnt09 < CAND_CAP ? cnt09 : CAND_CAP;
    /* if cnt09 < 300, top-300 may include s<0.9 items -> exact fallback below */
    const bool fast = (cnt09 >= PRE_NMS_K) && (cnt09 <= CAND_CAP);

    /* ---- histogram ---- */
    if (fast) {
        for (int i = tid; i < n09; i += NTHREADS) {
            float s = __uint_as_float((uint32_t)(cand[i] >> 32));
            int bin = (int)__fmul_rn(__fsub_rn(s, 0.9f), 40960.0f);
            bin = bin < NBINS - 1 ? bin : NBINS - 1;
            atomicAdd(&hist[bin], 1);
        }
    } else {
        const float2* cp = (const float2*)(cls_prob + (size_t)b * (NN * 2));
        for (int k = 0; k < NN / NTHREADS; k++) {
            int j = tid + k * NTHREADS;
            float s = cp[j].y;
            if (s >= 0.05f) {
                int bin = (int)__fmul_rn(__fsub_rn(s, 0.05f), (4096.0f / 0.95f));
                bin = bin < NBINS - 1 ? bin : NBINS - 1;
                atomicAdd(&hist[bin], 1);
            }
        }
    }
    __syncthreads();

    /* ---- suffix scan (4 bins/thread, top-down): bstar, selCnt,
            and per-bin rank offsets rankb[bin] = #items in bins > bin ---- */
    int base4 = NBINS - 4 * (tid + 1);
    int4 h0 = *(int4*)&hist[base4];     /* .x=hist[b], .y=+1, .z=+2, .w=+3 */
    int s4 = h0.x + h0.y + h0.z + h0.w;
    int v = s4;
#pragma unroll
    for (int off = 1; off < 32; off <<= 1) {
        int n = __shfl_up_sync(0xFFFFFFFFu, v, off);
        if (lane >= off) v += n;
    }
    if (lane == 31) wsums[wrp] = v;
    __syncthreads();
    if (wrp == 0) {
        int t = wsums[lane];
#pragma unroll
        for (int off = 1; off < 32; off <<= 1) {
            int n = __shfl_up_sync(0xFFFFFFFFu, t, off);
            if (lane >= off) t += n;
        }
        wsums[lane] = t;
    }
    __syncthreads();
    int inc = v + (wrp > 0 ? wsums[wrp - 1] : 0);
    int total = wsums[31];
    int target = total < PRE_NMS_K ? total : PRE_NMS_K;
    {
        int exc = inc - s4;             /* items in bins above this chunk */
        rankb[base4 + 3] = exc;
        rankb[base4 + 2] = exc + h0.w;
        rankb[base4 + 1] = exc + h0.w + h0.z;
        rankb[base4 + 0] = exc + h0.w + h0.z + h0.y;
        if (target > 0 && exc < target && target <= inc) {
            int cum = exc, bsel = base4;
            for (int u = 3; u >= 0; u--) {
                cum += hist[base4 + u];
                if (cum >= target) { bsel = base4 + u; break; }
            }
            scal[1] = bsel;
            scal[2] = cum;              /* selected count incl. full bstar bin */
        }
    }
    __syncthreads();
    int bstar = scal[1];
    int selCnt = scal[2];

    /* ---- rank scatter: each selected item lands in its bin's rank band ---- */
    if (fast) {
        for (int i = tid; i < n09; i += NTHREADS) {
            unsigned long long kk = cand[i];
            float s = __uint_as_float((uint32_t)(kk >> 32));
            int bin = (int)__fmul_rn(__fsub_rn(s, 0.9f), 40960.0f);
            bin = bin < NBINS - 1 ? bin : NBINS - 1;
            if (bin >= bstar) {
                int p = atomicAdd(&rankb[bin], 1);
                if (p < CAND_CAP) cand2[p] = kk;
            }
        }
    } else {
        const float2* cp = (const float2*)(cls_prob + (size_t)b * (NN * 2));
        for (int k = 0; k < NN / NTHREADS; k++) {
            int j = tid + k * NTHREADS;
            float s = cp[j].y;
            if (s >= 0.05f) {
                int bin = (int)__fmul_rn(__fsub_rn(s, 0.05f), (4096.0f / 0.95f));
                bin = bin < NBINS - 1 ? bin : NBINS - 1;
                if (bin >= bstar) {
                    int p = atomicAdd(&rankb[bin], 1);
                    if (p < CAND_CAP)
                        cand2[p] = ((unsigned long long)__float_as_uint(s) << 32) |
                                   (unsigned long long)(0xFFFFFFFFu - (uint32_t)j);
                }
            }
        }
    }
    __syncthreads();

    /* ---- intra-bin fixup: exact (score desc, idx asc) within each bin ---- */
    for (int bin = bstar + tid; bin < NBINS; bin += NTHREADS) {
        int h = hist[bin];
        if (h > 1) {
            int s0 = rankb[bin] - h;    /* post-scatter rankb = start + h */
            if (s0 >= 0 && rankb[bin] <= CAND_CAP) {
                for (int a2 = 1; a2 < h; a2++) {
                    unsigned long long key = cand2[s0 + a2];
                    int p = s0 + a2 - 1;
                    while (p >= s0 && cand2[p] < key) {
                        cand2[p + 1] = cand2[p];
                        p--;
                    }
                    cand2[p + 1] = key;
                }
            }
        }
    }
    __syncthreads();

    int L = selCnt < PRE_NMS_K ? selCnt : PRE_NMS_K;

    /* ---- Decode + clip selected boxes (rn intrinsics: no FMA contraction) ---- */
    if (tid < L) {
        unsigned long long kk = cand2[tid];
        int j = (int)(0xFFFFFFFFu - (uint32_t)(kk & 0xFFFFFFFFull));
        float4 bb = *(const float4*)(boxes  + ((size_t)b * NN + j) * 4);
        float4 dd = *(const float4*)(deltas + ((size_t)b * NN + j) * 4);
        float w  = __fadd_rn(__fsub_rn(bb.z, bb.x), 1.0f);
        float h  = __fadd_rn(__fsub_rn(bb.w, bb.y), 1.0f);
        float cx = __fadd_rn(bb.x, __fmul_rn(0.5f, w));
        float cy = __fadd_rn(bb.y, __fmul_rn(0.5f, h));
        float d0 = __fmul_rn(dd.x, 0.1f);
        float d1 = __fmul_rn(dd.y, 0.1f);
        float d2 = __fmul_rn(dd.z, 0.2f);
        float d3 = __fmul_rn(dd.w, 0.2f);
        float pcx = __fadd_rn(__fmul_rn(d0, w), cx);
        float pcy = __fadd_rn(__fmul_rn(d1, h), cy);
        float pw  = __fmul_rn((float)exp((double)d2), w);
        float ph  = __fmul_rn((float)exp((double)d3), h);
        float x1 = __fsub_rn(pcx, __fmul_rn(0.5f, pw));
        float y1 = __fsub_rn(pcy, __fmul_rn(0.5f, ph));
        float x2 = __fadd_rn(pcx, __fmul_rn(0.5f, pw));
        float y2 = __fadd_rn(pcy, __fmul_rn(0.5f, ph));
        float hmax = __fsub_rn(im_info[b * 3 + 0], 1.0f);
        float wmax = __fsub_rn(im_info[b * 3 + 1], 1.0f);
        x1 = fminf(fmaxf(x1, 0.0f), wmax);
        y1 = fminf(fmaxf(y1, 0.0f), hmax);
        x2 = fminf(fmaxf(x2, 0.0f), wmax);
        y2 = fminf(fmaxf(y2, 0.0f), hmax);
        bq[tid] = make_float4(x1, y1, x2, y2);
        barea[tid] = __fmul_rn(__fadd_rn(__fsub_rn(x2, x1), 1.0f),
                               __fadd_rn(__fsub_rn(y2, y1), 1.0f));
    }
    __syncthreads();

    /* ---- IoU suppression bitmasks (paired i-rows share j loads):
            mask[i] bit j set iff j>i && iou>0.3 ---- */
    for (int item = tid; item < NPAIR * MW; item += NTHREADS) {   /* 750 items */
        int ip = item / MW, w = item % MW;
        int i0 = 2 * ip, i1 = i0 + 1;
        if (i0 >= L) continue;
        float4 q0 = bq[i0];
        float  a0 = barea[i0];
        bool   has1 = (i1 < L);
        float4 q1 = has1 ? bq[i1] : q0;
        float  a1 = has1 ? barea[i1] : a0;
        unsigned long long bits0 = 0ull, bits1 = 0ull;
        int j0 = w * 64;
        int jend = (j0 + 64 < L) ? j0 + 64 : L;
        int jst = (j0 > i0 + 1) ? j0 : i0 + 1;
        for (int j = jst; j < jend; j++) {
            float4 qj = bq[j];
            float  aj = barea[j];
            {
                float xx1 = fmaxf(q0.x, qj.x);
                float yy1 = fmaxf(q0.y, qj.y);
                float xx2 = fminf(q0.z, qj.z);
                float yy2 = fminf(q0.w, qj.w);
                float iw = fmaxf(__fadd_rn(__fsub_rn(xx2, xx1), 1.0f), 0.0f);
                float ih = fmaxf(__fadd_rn(__fsub_rn(yy2, yy1), 1.0f), 0.0f);
                float inter = __fmul_rn(iw, ih);
                float uni = __fsub_rn(__fadd_rn(a0, aj), inter);
                float iou = __fdiv_rn(inter, uni);
                if ((j > i0) && (iou > 0.3f)) bits0 |= 1ull << (j - j0);
            }
            if (has1) {
                float xx1 = fmaxf(q1.x, qj.x);
                float yy1 = fmaxf(q1.y, qj.y);
                float xx2 = fminf(q1.z, qj.z);
                float yy2 = fminf(q1.w, qj.w);
                float iw = fmaxf(__fadd_rn(__fsub_rn(xx2, xx1), 1.0f), 0.0f);
                float ih = fmaxf(__fadd_rn(__fsub_rn(yy2, yy1), 1.0f), 0.0f);
                float inter = __fmul_rn(iw, ih);
                float uni = __fsub_rn(__fadd_rn(a1, aj), inter);
                float iou = __fdiv_rn(inter, uni);
                if ((j > i1) && (iou > 0.3f)) bits1 |= 1ull << (j - j0);
            }
        }
        maskA[i0 * MW + w] = bits0;
        if (has1) maskA[i1 * MW + w] = bits1;
    }
    __syncthreads();

    /* ---- Serial greedy NMS over bitmasks (thread 0) ---- */
    if (tid == 0) {
        unsigned long long r[MW] = {0ull, 0ull, 0ull, 0ull, 0ull};
#pragma unroll
        for (int w = 0; w < MW; w++) {
            int i0w = w * 64;
            if (i0w < L) {
                int iend = (i0w + 64 < L) ? i0w + 64 : L;
                for (int c0 = i0w; c0 < iend; c0 += 16) {
                    int ce = (c0 + 16 < iend) ? c0 + 16 : iend;
                    unsigned long long mm[16];
#pragma unroll
                    for (int t = 0; t < 16; t++)
                        mm[t] = (c0 + t < ce) ? maskA[(c0 + t) * MW + w] : 0ull;
#pragma unroll
                    for (int t = 0; t < 16; t++) {
                        int i = c0 + t;
                        if (i < ce && !((r[w] >> (i - i0w)) & 1ull))
                            r[w] |= mm[t];
                    }
                }
                int nb = iend - i0w;
                unsigned long long vm = (nb >= 64) ? ~0ull : ((1ull << nb) - 1ull);
                unsigned long long kw = (~r[w]) & vm;
                while (kw) {
                    int t = __ffsll((long long)kw) - 1;
                    kw &= kw - 1ull;
                    const unsigned long long* m = maskA + (i0w + t) * MW;
#pragma unroll
                    for (int w2 = 0; w2 < MW; w2++)
                        if (w2 > w) r[w2] |= m[w2];
                }
            }
        }
#pragma unroll
        for (int w = 0; w < MW; w++) {
            int lo = w * 64;
            unsigned long long vm = (L <= lo) ? 0ull
                                  : ((L - lo >= 64) ? ~0ull : ((1ull << (L - lo)) - 1ull));
            keepw[w] = (~r[w]) & vm;
        }
    }
    __syncthreads();

    /* ---- Output: scatter kept rows by rank (out already zeroed at start) ---- */
    if (tid < L) {
        int w = tid >> 6, bp = tid & 63;
        if ((keepw[w] >> bp) & 1ull) {
            int rank = 0;
            for (int u = 0; u < w; u++) rank += __popcll(keepw[u]);
            rank += __popcll(keepw[w] & ((1ull << bp) - 1ull));
            if (rank < POST_KK) {
                float4 q = bq[tid];
                float* row = outb + rank * 5;
                row[0] = (float)b;
                row[1] = q.x;
                row[2] = q.y;
                row[3] = q.z;
                row[4] = q.w;
            }
        }
    }
}

extern "C" void kernel_launch(void* const* d_in, const int* in_sizes, int n_in,
                              void* d_out, int out_size) {
    const float* cls_prob = (const float*)d_in[0];
    const float* boxes    = (const float*)d_in[1];
    const float* deltas   = (const float*)d_in[2];
    const float* im_info  = (const float*)d_in[3];
    int B = in_sizes[3] / 3;   /* im_info is (B,3) */
    cudaFuncSetAttribute(proposal_kernel,
                         cudaFuncAttributeMaxDynamicSharedMemorySize, SMEM_BYTES);
    proposal_kernel<<<B, NTHREADS, SMEM_BYTES>>>(cls_prob, boxes, deltas,
                                                 im_info, (float*)d_out);
}